// round 2
// baseline (speedup 1.0000x reference)
#include <cuda_runtime.h>
#include <math.h>

// ---------------------------------------------------------------------------
// MetaCNNLSTM: conv1d(64->256,k9,pad4) -> GN(8)+ReLU -> 3x LSTM(512) -> mean
// pool -> linear head.  B=32, T=512, fp32 everywhere.
// ---------------------------------------------------------------------------
#define BB   32
#define CIN  64
#define TT   512
#define FF   256
#define KK   9
#define GG   8
#define HH   512
#define G4   2048
#define NCLS 50
#define RNB  128    // persistent blocks in recurrence (must be co-resident)

// ------------------------- scratch (static device globals) -----------------
__device__ float   g_conv[BB * FF * TT];     // conv out (B,F,T)
__device__ float   g_xt[BB * TT * FF];       // GN+ReLU, (B*T, F)
__device__ float   g_xp[BB * TT * G4];       // input projections (B*T, 4H)
__device__ float   g_h1[BB * TT * HH];       // layer-1 output
__device__ float   g_h2[BB * TT * HH];       // layer-2 output
__device__ float   g_htb[2][HH * BB];        // h ping-pong, [unit][batch]
__device__ float   g_feat[BB * HH];          // pooled features
__device__ float2  g_stat[BB * GG];          // GN (mean, rstd)
__device__ unsigned g_cnt;                   // global barrier count
__device__ unsigned g_gen;                   // global barrier generation

// ------------------------------- conv1d ------------------------------------
// grid (T/128, B), 256 threads. dyn smem: xs[64][136] + ws[8][64][9]
#define CONV_SMEM ((64 * 136 + 8 * 64 * 9) * 4)
__global__ __launch_bounds__(256) void conv_kernel(
    const float* __restrict__ x, const float* __restrict__ w)
{
    extern __shared__ float sm[];
    float* xs = sm;              // [64][136]
    float* ws = sm + 64 * 136;   // [8][64][9]
    const int b   = blockIdx.y;
    const int t0  = blockIdx.x * 128;
    const int tid = threadIdx.x;

    for (int i = tid; i < 64 * 136; i += 256) {
        int c = i / 136, j = i - c * 136;
        int t = t0 - 4 + j;
        xs[i] = (t >= 0 && t < TT) ? x[(b * CIN + c) * TT + t] : 0.f;
    }
    const int lane = tid & 31;
    const int wf   = tid >> 5;      // local filter 0..7
    const int tl   = lane * 4;      // local t 0..124

    for (int fc = 0; fc < FF; fc += 8) {
        __syncthreads();
        for (int i = tid; i < 8 * 64 * 9; i += 256)
            ws[i] = w[fc * 64 * 9 + i];
        __syncthreads();
        const int f = fc + wf;
        float a0 = 0.f, a1 = 0.f, a2 = 0.f, a3 = 0.f;
        for (int c = 0; c < 64; ++c) {
            const float* xr = &xs[c * 136 + tl];
            const float* wr = &ws[(wf * 64 + c) * 9];
            float4 p0 = *(const float4*)(xr);
            float4 p1 = *(const float4*)(xr + 4);
            float4 p2 = *(const float4*)(xr + 8);
            float xv[12] = {p0.x, p0.y, p0.z, p0.w, p1.x, p1.y, p1.z, p1.w,
                            p2.x, p2.y, p2.z, p2.w};
#pragma unroll
            for (int k = 0; k < 9; ++k) {
                float wk = wr[k];
                a0 += wk * xv[k];
                a1 += wk * xv[k + 1];
                a2 += wk * xv[k + 2];
                a3 += wk * xv[k + 3];
            }
        }
        *(float4*)&g_conv[(b * FF + f) * TT + t0 + tl] =
            make_float4(a0, a1, a2, a3);
    }
}

// ------------------------------ groupnorm stats ------------------------------
__global__ __launch_bounds__(256) void gn_stats_kernel()
{
    const int b = blockIdx.x >> 3, g = blockIdx.x & 7;
    __shared__ float ssum[256], ssq[256];
    const int tid = threadIdx.x;
    const float* base = g_conv + (b * FF + g * 32) * TT;
    float s = 0.f, q = 0.f;
    for (int i = tid; i < 32 * TT; i += 256) {
        float v = base[i];
        s += v; q += v * v;
    }
    ssum[tid] = s; ssq[tid] = q;
    __syncthreads();
    for (int o = 128; o > 0; o >>= 1) {
        if (tid < o) { ssum[tid] += ssum[tid + o]; ssq[tid] += ssq[tid + o]; }
        __syncthreads();
    }
    if (tid == 0) {
        float mean = ssum[0] * (1.f / 16384.f);
        float var  = ssq[0] * (1.f / 16384.f) - mean * mean;
        g_stat[b * GG + g] = make_float2(mean, rsqrtf(var + 1e-5f));
    }
}

// -------- GN apply + ReLU + transpose (B,F,T) -> (B*T, F) -------------------
// grid (T/32, F/32, B), 256 threads
__global__ __launch_bounds__(256) void gn_apply_kernel(
    const float* __restrict__ gamma, const float* __restrict__ beta)
{
    __shared__ float tile[32][33];
    const int b  = blockIdx.z;
    const int f0 = blockIdx.y * 32;
    const int t0 = blockIdx.x * 32;
    const int tx = threadIdx.x & 31, ty = threadIdx.x >> 5;   // ty 0..7
#pragma unroll
    for (int j = 0; j < 4; ++j) {
        int f = f0 + ty + j * 8;
        float2 st = g_stat[b * GG + (f >> 5)];
        float v = g_conv[(b * FF + f) * TT + t0 + tx];
        v = (v - st.x) * st.y * gamma[f] + beta[f];
        tile[ty + j * 8][tx] = fmaxf(v, 0.f);
    }
    __syncthreads();
#pragma unroll
    for (int j = 0; j < 4; ++j) {
        int t = t0 + ty + j * 8;
        g_xt[(b * TT + t) * FF + f0 + tx] = tile[tx][ty + j * 8];
    }
}

// --------------------- projection GEMM: C = A @ B^T + bias ------------------
// A: (M, Ka) row-major. Bm: (2048, Ka) row-major. C: (M, 2048).
// grid (N/64=32, M/64), 256 threads, 64x64 tile, 4x4 per thread.
__global__ __launch_bounds__(256) void gemm_kernel(
    const float* __restrict__ A, const float* __restrict__ Bm,
    const float* __restrict__ bias, float* __restrict__ C, int Ka)
{
    __shared__ float As[16][64];
    __shared__ float Bs[16][64];
    const int bm = blockIdx.y * 64, bn = blockIdx.x * 64;
    const int tid = threadIdx.x;
    const int lm  = tid >> 2;            // 0..63
    const int lk4 = (tid & 3) * 4;       // 0,4,8,12
    const int tm  = (tid & 15) * 4;
    const int tn  = (tid >> 4) * 4;

    float acc[4][4];
#pragma unroll
    for (int i = 0; i < 4; ++i)
#pragma unroll
        for (int j = 0; j < 4; ++j) acc[i][j] = 0.f;

    for (int ko = 0; ko < Ka; ko += 16) {
        float4 av = *(const float4*)&A[(bm + lm) * Ka + ko + lk4];
        float4 bv = *(const float4*)&Bm[(bn + lm) * Ka + ko + lk4];
        __syncthreads();
        As[lk4 + 0][lm] = av.x; As[lk4 + 1][lm] = av.y;
        As[lk4 + 2][lm] = av.z; As[lk4 + 3][lm] = av.w;
        Bs[lk4 + 0][lm] = bv.x; Bs[lk4 + 1][lm] = bv.y;
        Bs[lk4 + 2][lm] = bv.z; Bs[lk4 + 3][lm] = bv.w;
        __syncthreads();
#pragma unroll
        for (int k = 0; k < 16; ++k) {
            float4 a4 = *(const float4*)&As[k][tm];
            float4 b4 = *(const float4*)&Bs[k][tn];
            float am[4] = {a4.x, a4.y, a4.z, a4.w};
            float bn4[4] = {b4.x, b4.y, b4.z, b4.w};
#pragma unroll
            for (int i = 0; i < 4; ++i)
#pragma unroll
                for (int j = 0; j < 4; ++j) acc[i][j] += am[i] * bn4[j];
        }
    }
#pragma unroll
    for (int i = 0; i < 4; ++i) {
        int row = bm + tm + i;
#pragma unroll
        for (int j = 0; j < 4; ++j)
            C[row * G4 + bn + tn + j] = acc[i][j] + bias[bn + tn + j];
    }
}

// ----------------------- zero ping-pong h buffer ---------------------------
__global__ void zero_h_kernel()
{
    int i = blockIdx.x * 256 + threadIdx.x;   // grid 64 -> 16384
    __stcg(&g_htb[0][i], 0.f);
}

// ------------------------- persistent recurrence ---------------------------
__device__ __forceinline__ void grid_bar()
{
    __syncthreads();
    if (threadIdx.x == 0) {
        unsigned gen = *(volatile unsigned*)&g_gen;
        __threadfence();
        if (atomicAdd(&g_cnt, 1u) == RNB - 1) {
            g_cnt = 0;
            __threadfence();
            atomicAdd(&g_gen, 1u);
        } else {
            while (*(volatile unsigned*)&g_gen == gen) __nanosleep(40);
        }
    }
    __syncthreads();
}

#define REC_SMEM ((HH * BB + 16 * 16 * 32) * 4)   // 64KB h + 32KB partials
__global__ __launch_bounds__(256) void rec_kernel(
    const float* __restrict__ w_hh, const float* __restrict__ xp,
    float* __restrict__ out, int do_pool)
{
    extern __shared__ float sm[];
    float* h_sm = sm;             // [512][32]
    float* part = sm + HH * BB;   // [16 slots][16 rows][32 b]
    const int tid  = threadIdx.x;
    const int w    = tid >> 5;
    const int lane = tid & 31;
    const int r    = lane & 15;       // row 0..15  (gate*4 + u)
    const int half = lane >> 4;
    const int k0   = w * 64 + half * 32;
    const int gate = r >> 2;
    const int u    = r & 3;
    const int ug   = blockIdx.x * 4 + u;

    // W_hh slice -> registers (fixed for whole layer)
    float wreg[32];
    {
        const float* wp = &w_hh[(gate * HH + ug) * HH + k0];
#pragma unroll
        for (int i = 0; i < 8; ++i) {
            float4 v = *(const float4*)(wp + i * 4);
            wreg[i * 4]     = v.x; wreg[i * 4 + 1] = v.y;
            wreg[i * 4 + 2] = v.z; wreg[i * 4 + 3] = v.w;
        }
    }
    // cell-thread mapping (tid < 128): (unit cu, batch cb)
    const int cu  = tid >> 5;
    const int cb  = tid & 31;
    const int cug = blockIdx.x * 4 + cu;
    float c_state = 0.f, hsum = 0.f;

    for (int t = 0; t < TT; ++t) {
        const int p = t & 1;
        // stage h_prev (L2 only; stcg/ldcg for coherence) -> smem
        const float4* src = (const float4*)(g_htb[p]);
#pragma unroll
        for (int i = 0; i < 16; ++i) {
            int idx = tid + i * 256;
            ((float4*)h_sm)[idx] = __ldcg(src + idx);
        }
        // prefetch input projections for the cell update
        float xg[4] = {0.f, 0.f, 0.f, 0.f};
        if (tid < 128) {
            const float* xpp = xp + (cb * TT + t) * G4 + cug;
#pragma unroll
            for (int gg = 0; gg < 4; ++gg) xg[gg] = xpp[gg * HH];
        }
        __syncthreads();

        float acc[32];
#pragma unroll
        for (int b = 0; b < 32; ++b) acc[b] = 0.f;
#pragma unroll
        for (int kk = 0; kk < 32; ++kk) {
            float wv = wreg[kk];
            const float* hp = h_sm + (k0 + kk) * 32;
#pragma unroll
            for (int b4 = 0; b4 < 32; b4 += 4) {
                float4 hv = *(const float4*)(hp + b4);
                acc[b4]     += wv * hv.x;
                acc[b4 + 1] += wv * hv.y;
                acc[b4 + 2] += wv * hv.z;
                acc[b4 + 3] += wv * hv.w;
            }
        }
        // write partials: slot = w*2+half
        {
            float* pp = part + ((w * 2 + half) * 16 + r) * 32;
#pragma unroll
            for (int b4 = 0; b4 < 32; b4 += 4)
                *(float4*)(pp + b4) =
                    make_float4(acc[b4], acc[b4 + 1], acc[b4 + 2], acc[b4 + 3]);
        }
        __syncthreads();

        if (tid < 128) {
            float gsum[4];
#pragma unroll
            for (int gg = 0; gg < 4; ++gg) {
                int row = gg * 4 + cu;
                float s = xg[gg];
#pragma unroll
                for (int sl = 0; sl < 16; ++sl)
                    s += part[(sl * 16 + row) * 32 + cb];
                gsum[gg] = s;
            }
            float ig  = 1.f / (1.f + __expf(-gsum[0]));
            float fg  = 1.f / (1.f + __expf(-gsum[1]));
            float gg_ = tanhf(gsum[2]);
            float og  = 1.f / (1.f + __expf(-gsum[3]));
            c_state = fg * c_state + ig * gg_;
            float hv = og * tanhf(c_state);
            __stcg(&g_htb[p ^ 1][cug * 32 + cb], hv);
            if (out) out[(cb * TT + t) * HH + cug] = hv;
            hsum += hv;
        }
        grid_bar();
    }
    if (do_pool && tid < 128)
        g_feat[cb * HH + cug] = hsum * (1.f / 512.f);
}

// --------------------------------- head ------------------------------------
// grid (NCLS, B), 64 threads
__global__ __launch_bounds__(64) void head_kernel(
    const float* __restrict__ hw, const float* __restrict__ hb,
    float* __restrict__ outp)
{
    const int c = blockIdx.x, b = blockIdx.y;
    float s = 0.f;
    for (int k = threadIdx.x; k < HH; k += 64)
        s += g_feat[b * HH + k] * hw[c * HH + k];
    __shared__ float red[2];
#pragma unroll
    for (int o = 16; o; o >>= 1) s += __shfl_down_sync(0xffffffffu, s, o);
    if ((threadIdx.x & 31) == 0) red[threadIdx.x >> 5] = s;
    __syncthreads();
    if (threadIdx.x == 0) outp[b * NCLS + c] = red[0] + red[1] + hb[c];
}

// ------------------------------ launcher -----------------------------------
extern "C" void kernel_launch(void* const* d_in, const int* in_sizes, int n_in,
                              void* d_out, int out_size)
{
    const float* x_emg  = (const float*)d_in[0];
    const float* conv_w = (const float*)d_in[1];
    const float* gamma  = (const float*)d_in[2];
    const float* beta   = (const float*)d_in[3];
    const float *w_ih[3], *w_hh[3], *bi[3], *head_w, *head_b;

    if (in_sizes[4] == 4 * HH * FF) {          // signature order
        for (int l = 0; l < 3; ++l) {
            w_ih[l] = (const float*)d_in[4 + 3 * l];
            w_hh[l] = (const float*)d_in[5 + 3 * l];
            bi[l]   = (const float*)d_in[6 + 3 * l];
        }
        head_w = (const float*)d_in[13];
        head_b = (const float*)d_in[14];
    } else {                                    // dict order
        head_w = (const float*)d_in[4];
        head_b = (const float*)d_in[5];
        for (int l = 0; l < 3; ++l) {
            w_ih[l] = (const float*)d_in[6 + 3 * l];
            w_hh[l] = (const float*)d_in[7 + 3 * l];
            bi[l]   = (const float*)d_in[8 + 3 * l];
        }
    }
    float* out = (float*)d_out;

    cudaFuncSetAttribute(conv_kernel,
        cudaFuncAttributeMaxDynamicSharedMemorySize, CONV_SMEM);
    cudaFuncSetAttribute(rec_kernel,
        cudaFuncAttributeMaxDynamicSharedMemorySize, REC_SMEM);

    float* g_xp_p;   cudaGetSymbolAddress((void**)&g_xp_p, g_xp);
    float* g_xt_p;   cudaGetSymbolAddress((void**)&g_xt_p, g_xt);
    float* g_h1_p;   cudaGetSymbolAddress((void**)&g_h1_p, g_h1);
    float* g_h2_p;   cudaGetSymbolAddress((void**)&g_h2_p, g_h2);

    // conv + groupnorm + relu + transpose
    conv_kernel<<<dim3(TT / 128, BB), 256, CONV_SMEM>>>(x_emg, conv_w);
    gn_stats_kernel<<<BB * GG, 256>>>();
    gn_apply_kernel<<<dim3(TT / 32, FF / 32, BB), 256>>>(gamma, beta);

    const float* lay_in[3] = {g_xt_p, g_h1_p, g_h2_p};
    float*       lay_out[3] = {g_h1_p, g_h2_p, nullptr};
    const int    lay_ka[3] = {FF, HH, HH};

    for (int l = 0; l < 3; ++l) {
        gemm_kernel<<<dim3(G4 / 64, BB * TT / 64), 256>>>(
            lay_in[l], w_ih[l], bi[l], g_xp_p, lay_ka[l]);
        zero_h_kernel<<<64, 256>>>();
        rec_kernel<<<RNB, 256, REC_SMEM>>>(w_hh[l], g_xp_p, lay_out[l],
                                           l == 2 ? 1 : 0);
    }
    head_kernel<<<dim3(NCLS, BB), 64>>>(head_w, head_b, out);
}